// round 2
// baseline (speedup 1.0000x reference)
#include <cuda_runtime.h>
#include <math.h>

#define NN      1023
#define NLEAVES 512
#define HD      300
#define NB      900

typedef unsigned long long ull;

// ---------------- static device scratch ----------------
__device__ float g_Wxp[HD * NB];     // packed W_ix|W_fx|W_ux, [k][c]
__device__ float g_Whp[HD * NB];     // packed W_ih|W_fh|W_uh
__device__ float g_XX[NN * NB];      // x @ Wxp (raw, no bias)
__device__ float g_G[2 * 256 * NB];  // per-level child GEMM results (max 512 rows)
__device__ float g_h[NN * HD];
__device__ float g_c[NN * HD];
__device__ float g_loss[NN];
__device__ float g_logp_scratch[NN * 5];

// ---------------- f32x2 helpers ----------------
static __device__ __forceinline__ ull pack2(float x, float y) {
    ull r;
    asm("mov.b64 %0, {%1, %2};" : "=l"(r) : "f"(x), "f"(y));
    return r;
}
static __device__ __forceinline__ void unpack2(ull v, float &x, float &y) {
    asm("mov.b64 {%0, %1}, %2;" : "=f"(x), "=f"(y) : "l"(v));
}
static __device__ __forceinline__ void ffma2(ull &d, ull a, ull b) {
    asm("fma.rn.f32x2 %0, %1, %2, %0;" : "+l"(d) : "l"(a), "l"(b));
}
static __device__ __forceinline__ float sigf(float x) {
    return 1.0f / (1.0f + expf(-x));
}

// ---------------- pack weights into [300][900] strips ----------------
__global__ void pack_w(const float* __restrict__ Wix, const float* __restrict__ Wfx,
                       const float* __restrict__ Wux, const float* __restrict__ Wih,
                       const float* __restrict__ Wfh, const float* __restrict__ Wuh)
{
    int idx = blockIdx.x * blockDim.x + threadIdx.x;
    if (idx >= HD * NB) return;
    int k = idx / NB, c = idx % NB;
    int g = c / HD, j = c % HD;
    const float* wx = (g == 0) ? Wix : (g == 1) ? Wfx : Wux;
    const float* wh = (g == 0) ? Wih : (g == 1) ? Wfh : Wuh;
    g_Wxp[idx] = wx[k * HD + j];
    g_Whp[idx] = wh[k * HD + j];
}

// ---------------- gathered GEMM: out[M x 900] = gather(src,rowIdx)[M x 300] @ B ---------
// mode 0: src = emb (param), B = g_Wxp, out = g_XX
// mode 1: src = g_h,         B = g_Whp, out = g_G
__global__ __launch_bounds__(256) void gemm64(const float* __restrict__ src_param,
                                              const int* __restrict__ rowIdx,
                                              int M, int mode)
{
    __shared__ float As[16][66];
    __shared__ __align__(16) float Bs[16][64];

    const float* __restrict__ src = (mode == 0) ? src_param : g_h;
    const float* __restrict__ B   = (mode == 0) ? g_Wxp : g_Whp;
    float* __restrict__ out       = (mode == 0) ? g_XX : g_G;

    const int tid = threadIdx.x;
    const int tx = tid & 15, ty = tid >> 4;
    const int m0 = blockIdx.y * 64, n0 = blockIdx.x * 64;

    // per-thread fixed A-row bases (m depends only on tid)
    int abase[4];
#pragma unroll
    for (int i = 0; i < 4; i++) {
        int m = (tid + i * 256) >> 4;
        int gm = m0 + m;
        abase[i] = (gm < M) ? rowIdx[gm] * HD : -1;
    }

    ull acc[4][2];
#pragma unroll
    for (int i = 0; i < 4; i++) { acc[i][0] = pack2(0.f, 0.f); acc[i][1] = pack2(0.f, 0.f); }

    for (int k0 = 0; k0 < HD; k0 += 16) {
#pragma unroll
        for (int i = 0; i < 4; i++) {
            int idx = tid + i * 256;
            int m = idx >> 4, k = idx & 15;
            int gk = k0 + k;
            float v = 0.f;
            if (abase[i] >= 0 && gk < HD) v = src[abase[i] + gk];
            As[k][m] = v;
        }
#pragma unroll
        for (int i = 0; i < 4; i++) {
            int idx = tid + i * 256;
            int k = idx >> 6, n = idx & 63;
            int gk = k0 + k, gn = n0 + n;
            float v = 0.f;
            if (gk < HD && gn < NB) v = B[gk * NB + gn];
            Bs[k][n] = v;
        }
        __syncthreads();

#pragma unroll
        for (int k = 0; k < 16; k++) {
            float2 b01 = *(const float2*)&Bs[k][tx * 4];
            float2 b23 = *(const float2*)&Bs[k][tx * 4 + 2];
            ull bp0 = pack2(b01.x, b01.y);
            ull bp1 = pack2(b23.x, b23.y);
#pragma unroll
            for (int i = 0; i < 4; i++) {
                float a = As[k][ty * 4 + i];
                ull ap = pack2(a, a);
                ffma2(acc[i][0], ap, bp0);
                ffma2(acc[i][1], ap, bp1);
            }
        }
        __syncthreads();
    }

#pragma unroll
    for (int i = 0; i < 4; i++) {
        int gm = m0 + ty * 4 + i;
        if (gm >= M) continue;
        float x0, x1, x2, x3;
        unpack2(acc[i][0], x0, x1);
        unpack2(acc[i][1], x2, x3);
        int gn = n0 + tx * 4;
        float* o = out + (size_t)gm * NB + gn;
        if (gn + 3 < NB) { o[0] = x0; o[1] = x1; o[2] = x2; o[3] = x3; }
        else {
            if (gn     < NB) o[0] = x0;
            if (gn + 1 < NB) o[1] = x1;
            if (gn + 2 < NB) o[2] = x2;
            if (gn + 3 < NB) o[3] = x3;
        }
    }
}

// ---------------- leaves: c = sig(i)*sig(u), h = sig(o)*tanh(c) ----------------
__global__ void leaves_kernel(const float* __restrict__ bix, const float* __restrict__ bfx,
                              const float* __restrict__ bux, const float* __restrict__ bih,
                              const float* __restrict__ bfh, const float* __restrict__ buh)
{
    int idx = blockIdx.x * blockDim.x + threadIdx.x;
    if (idx >= NLEAVES * HD) return;
    int t = idx / HD, j = idx % HD;
    const float* xx = g_XX + (size_t)t * NB;
    float i = sigf(xx[j]        + bix[j] + bih[j]);
    float o = sigf(xx[HD + j]   + bfx[j] + bfh[j]);
    float u = sigf(xx[2*HD + j] + bux[j] + buh[j]);
    float c = i * u;
    g_c[t * HD + j] = c;
    g_h[t * HD + j] = o * tanhf(c);
}

// ---------------- per-level fused LSTM cell epilogue ----------------
__global__ void level_epi(int base, int Wd, const int* __restrict__ children,
                          const float* __restrict__ bix, const float* __restrict__ bfx,
                          const float* __restrict__ bux, const float* __restrict__ bih,
                          const float* __restrict__ bfh, const float* __restrict__ buh)
{
    int idx = blockIdx.x * blockDim.x + threadIdx.x;
    if (idx >= Wd * HD) return;
    int p = idx / HD, j = idx % HD;
    int t = base + p;
    const float* xx = g_XX + (size_t)t * NB;
    const float* G0 = g_G + (size_t)(2 * p) * NB;
    const float* G1 = G0 + NB;

    float ixx = xx[j]          + bix[j];
    float fxx = xx[HD + j]     + bfx[j];
    float uxx = xx[2 * HD + j] + bux[j];
    float bf  = bfh[j];

    float g0f = G0[HD + j], g1f = G1[HD + j];

    float i = sigf(ixx + G0[j]          + G1[j]          + bih[j]);
    float o = sigf(fxx + g0f            + g1f            + bf);
    float u = sigf(uxx + G0[2 * HD + j] + G1[2 * HD + j] + buh[j]);
    float f0 = sigf(g0f + bf + fxx);
    float f1 = sigf(g1f + bf + fxx);

    int c0 = children[2 * p], c1 = children[2 * p + 1];
    float cc = i * u + f0 * g_c[c0 * HD + j] + f1 * g_c[c1 * HD + j];
    g_c[t * HD + j] = cc;
    g_h[t * HD + j] = o * tanhf(cc);
}

// ---------------- output: logits, log_softmax, per-node loss ----------------
__global__ __launch_bounds__(128) void out_kernel(const float* __restrict__ Wout,
                                                  const float* __restrict__ bout,
                                                  const int* __restrict__ labels,
                                                  float* __restrict__ out, int logp_to_out)
{
    int t = blockIdx.x;
    int tid = threadIdx.x;
    float acc[5] = {0.f, 0.f, 0.f, 0.f, 0.f};
    const float* h = g_h + (size_t)t * HD;
    for (int j = tid; j < HD; j += 128) {
        float hv = h[j];
#pragma unroll
        for (int l = 0; l < 5; l++) acc[l] += hv * Wout[j * 5 + l];
    }
#pragma unroll
    for (int off = 16; off > 0; off >>= 1) {
#pragma unroll
        for (int l = 0; l < 5; l++)
            acc[l] += __shfl_down_sync(0xffffffffu, acc[l], off);
    }
    __shared__ float s[4][5];
    int w = tid >> 5, lane = tid & 31;
    if (lane == 0) {
#pragma unroll
        for (int l = 0; l < 5; l++) s[w][l] = acc[l];
    }
    __syncthreads();
    if (tid == 0) {
        float lg[5];
#pragma unroll
        for (int l = 0; l < 5; l++)
            lg[l] = s[0][l] + s[1][l] + s[2][l] + s[3][l] + bout[l];
        float mx = lg[0];
#pragma unroll
        for (int l = 1; l < 5; l++) mx = fmaxf(mx, lg[l]);
        float se = 0.f;
#pragma unroll
        for (int l = 0; l < 5; l++) se += expf(lg[l] - mx);
        float lse = mx + logf(se);
        float* dst = logp_to_out ? (out + (size_t)t * 5) : (g_logp_scratch + (size_t)t * 5);
#pragma unroll
        for (int l = 0; l < 5; l++) dst[l] = lg[l] - lse;
        g_loss[t] = -(lg[labels[t]] - lse);
    }
}

__global__ void loss_reduce(float* __restrict__ outloss)
{
    __shared__ float s[1024];
    int tid = threadIdx.x;
    float v = 0.f;
    for (int i = tid; i < NN; i += 1024) v += g_loss[i];
    s[tid] = v;
    __syncthreads();
    for (int st = 512; st > 0; st >>= 1) {
        if (tid < st) s[tid] += s[tid + st];
        __syncthreads();
    }
    if (tid == 0) *outloss = s[0];
}

// ---------------- launch ----------------
extern "C" void kernel_launch(void* const* d_in, const int* in_sizes, int n_in,
                              void* d_out, int out_size)
{
    const int*   word_ids = (const int*)d_in[0];
    const int*   labels   = (const int*)d_in[1];
    const int*   children = (const int*)d_in[2];
    // d_in[3] children_mask: implied by tree structure (0 for leaves, 1 internal)
    const float* emb = (const float*)d_in[4];
    const float* Wix = (const float*)d_in[5],  *bix = (const float*)d_in[6];
    const float* Wih = (const float*)d_in[7],  *bih = (const float*)d_in[8];
    const float* Wfx = (const float*)d_in[9],  *bfx = (const float*)d_in[10];
    const float* Wfh = (const float*)d_in[11], *bfh = (const float*)d_in[12];
    const float* Wux = (const float*)d_in[13], *bux = (const float*)d_in[14];
    const float* Wuh = (const float*)d_in[15], *buh = (const float*)d_in[16];
    const float* Wout = (const float*)d_in[17], *bout = (const float*)d_in[18];
    float* out = (float*)d_out;

    // 1. pack weight strips
    pack_w<<<(HD * NB + 255) / 256, 256>>>(Wix, Wfx, Wux, Wih, Wfh, Wuh);

    // 2. prologue GEMM: g_XX = emb[word_ids] @ Wxp
    gemm64<<<dim3((NB + 63) / 64, (NN + 63) / 64), 256>>>(emb, word_ids, NN, 0);

    // 3. leaves (512 parallel)
    leaves_kernel<<<(NLEAVES * HD + 255) / 256, 256>>>(bix, bfx, bux, bih, bfh, buh);

    // 4. 9 sequential levels: gathered GEMM on child h rows + fused cell epilogue
    static const int bases[9]  = {512, 768, 896, 960, 992, 1008, 1016, 1020, 1022};
    static const int widths[9] = {256, 128, 64, 32, 16, 8, 4, 2, 1};
    for (int l = 0; l < 9; l++) {
        int Wd = widths[l], base = bases[l];
        int M = 2 * Wd;
        gemm64<<<dim3((NB + 63) / 64, (M + 63) / 64), 256>>>(nullptr, children + 2 * base, M, 1);
        int nth = Wd * HD;
        level_epi<<<(nth + 255) / 256, 256>>>(base, Wd, children + 2 * base,
                                              bix, bfx, bux, bih, bfh, buh);
    }

    // 5. logits + log_softmax + per-node loss
    int logp_to_out = (out_size >= NN * 5) ? 1 : 0;
    out_kernel<<<NN, 128>>>(Wout, bout, labels, out, logp_to_out);

    // 6. loss reduction into output
    if (out_size > NN * 5) {
        loss_reduce<<<1, 1024>>>(out + NN * 5);
    } else if (out_size < NN * 5) {
        loss_reduce<<<1, 1024>>>(out);
    }
}